// round 1
// baseline (speedup 1.0000x reference)
#include <cuda_runtime.h>

#define Nn 2048
#define Dd 1024
#define Hh 16
#define HD 64
#define NEMB 199
#define RAD 99
#define PST 256   // row stride of pos scratch

// ---------------- scratch (device globals; no allocation) ----------------
__device__ float g_q[Hh * Nn * HD];        // [h][n][d]
__device__ float g_k[Hh * Nn * HD];        // [h][n][d], pre-scaled by 1/8
__device__ float g_v[Hh * Nn * HD];        // [h][n][d]
__device__ float g_pos[Hh * Nn * PST];     // [h][i][r<199], stride 256
__device__ float g_ao[Nn * Dd];            // attention output [n][h*64+d]

// ---------------- SGEMM: C[n][m] = sum_k A[n][k]*B[m][k] + bias[m] --------
// MODE 0: write q/k/v split (A = x, B = qkv_w)
// MODE 1: write out[n][m]   (A = g_ao, B = proj_w)
template <int MODE>
__global__ void __launch_bounds__(256) sgemm_nt(
    const float* __restrict__ Ain, const float* __restrict__ B,
    const float* __restrict__ bias, float* __restrict__ out,
    int M, int Nc, int K)
{
    const float* A = (MODE == 1) ? (const float*)g_ao : Ain;
    __shared__ float As[16][128];
    __shared__ float Bs[16][128];

    int t  = threadIdx.x;
    int tx = t & 15, ty = t >> 4;
    int n0 = blockIdx.y * 128;
    int m0 = blockIdx.x * 128;
    int lr = t >> 2;            // 0..63
    int lk = (t & 3) << 2;      // 0,4,8,12

    float acc[8][8];
#pragma unroll
    for (int i = 0; i < 8; i++)
#pragma unroll
        for (int j = 0; j < 8; j++) acc[i][j] = 0.f;

    for (int k0 = 0; k0 < K; k0 += 16) {
        float4 a0 = *(const float4*)(A + (size_t)(n0 + lr) * K + k0 + lk);
        float4 a1 = *(const float4*)(A + (size_t)(n0 + 64 + lr) * K + k0 + lk);
        float4 b0 = *(const float4*)(B + (size_t)(m0 + lr) * K + k0 + lk);
        float4 b1 = *(const float4*)(B + (size_t)(m0 + 64 + lr) * K + k0 + lk);

        As[lk + 0][lr] = a0.x; As[lk + 1][lr] = a0.y; As[lk + 2][lr] = a0.z; As[lk + 3][lr] = a0.w;
        As[lk + 0][64 + lr] = a1.x; As[lk + 1][64 + lr] = a1.y; As[lk + 2][64 + lr] = a1.z; As[lk + 3][64 + lr] = a1.w;
        Bs[lk + 0][lr] = b0.x; Bs[lk + 1][lr] = b0.y; Bs[lk + 2][lr] = b0.z; Bs[lk + 3][lr] = b0.w;
        Bs[lk + 0][64 + lr] = b1.x; Bs[lk + 1][64 + lr] = b1.y; Bs[lk + 2][64 + lr] = b1.z; Bs[lk + 3][64 + lr] = b1.w;
        __syncthreads();

#pragma unroll
        for (int kk = 0; kk < 16; kk++) {
            float av[8], bv[8];
            *(float4*)&av[0] = *(float4*)&As[kk][ty * 4];
            *(float4*)&av[4] = *(float4*)&As[kk][64 + ty * 4];
            *(float4*)&bv[0] = *(float4*)&Bs[kk][tx * 4];
            *(float4*)&bv[4] = *(float4*)&Bs[kk][64 + tx * 4];
#pragma unroll
            for (int i = 0; i < 8; i++)
#pragma unroll
                for (int j = 0; j < 8; j++) acc[i][j] += av[i] * bv[j];
        }
        __syncthreads();
    }

#pragma unroll
    for (int i = 0; i < 8; i++) {
        int n = n0 + ((i < 4) ? (ty * 4 + i) : (64 + ty * 4 + i - 4));
#pragma unroll
        for (int j = 0; j < 8; j++) {
            int m = m0 + ((j < 4) ? (tx * 4 + j) : (64 + tx * 4 + j - 4));
            float v = acc[i][j] + bias[m];
            if (MODE == 0) {
                int sec = m >> 10;
                int hm = m & 1023;
                int h = hm >> 6, d = hm & 63;
                if (sec == 1) v *= 0.125f;  // fold 1/sqrt(64) into k
                float* p = (sec == 0) ? g_q : ((sec == 1) ? g_k : g_v);
                p[((h * Nn + n) << 6) + d] = v;
            } else {
                out[(size_t)n * Nc + m] = v;
            }
        }
    }
}

// ---------------- pos logits: P[h][i][r] = q[h,i,:] . rel_emb[h,r,:] ------
#define ESTR 232
#define POS_SMEM_FLOATS (64 * 32 + 64 * ESTR)

__global__ void __launch_bounds__(256) pos_kernel(const float* __restrict__ rel_emb)
{
    extern __shared__ float sm[];
    float* sQt = sm;              // [64][32]
    float* sEt = sm + 64 * 32;    // [64][ESTR], cols 0..198 valid

    int h = blockIdx.y;
    int i0 = blockIdx.x * 32;
    int t = threadIdx.x;

    for (int idx = t; idx < 32 * 16; idx += 256) {
        int qi = idx >> 4, dq = (idx & 15) << 2;
        float4 v = *(const float4*)&g_q[((h * Nn + i0 + qi) << 6) + dq];
        sQt[(dq + 0) * 32 + qi] = v.x; sQt[(dq + 1) * 32 + qi] = v.y;
        sQt[(dq + 2) * 32 + qi] = v.z; sQt[(dq + 3) * 32 + qi] = v.w;
    }
    const float* E = rel_emb + (size_t)h * NEMB * HD;
    for (int idx = t; idx < NEMB * 16; idx += 256) {
        int r = idx >> 4, dq = (idx & 15) << 2;
        float4 v = *(const float4*)&E[r * HD + dq];
        sEt[(dq + 0) * ESTR + r] = v.x; sEt[(dq + 1) * ESTR + r] = v.y;
        sEt[(dq + 2) * ESTR + r] = v.z; sEt[(dq + 3) * ESTR + r] = v.w;
    }
    __syncthreads();

    int tx = t & 31, ty = t >> 5;
    float acc[4][8];
#pragma unroll
    for (int i = 0; i < 4; i++)
#pragma unroll
        for (int j = 0; j < 8; j++) acc[i][j] = 0.f;

    for (int k = 0; k < 64; k++) {
        float4 a  = *(float4*)&sQt[k * 32 + ty * 4];
        float4 b0 = *(float4*)&sEt[k * ESTR + tx * 4];
        float4 b1 = *(float4*)&sEt[k * ESTR + 104 + tx * 4];
        float av[4] = {a.x, a.y, a.z, a.w};
        float bv[8] = {b0.x, b0.y, b0.z, b0.w, b1.x, b1.y, b1.z, b1.w};
#pragma unroll
        for (int i = 0; i < 4; i++)
#pragma unroll
            for (int j = 0; j < 8; j++) acc[i][j] += av[i] * bv[j];
    }

#pragma unroll
    for (int i = 0; i < 4; i++) {
        int ii = i0 + ty * 4 + i;
#pragma unroll
        for (int j = 0; j < 8; j++) {
            int r = (j < 4) ? (tx * 4 + j) : (104 + tx * 4 + j - 4);
            if (r < NEMB) g_pos[(size_t)(h * Nn + ii) * PST + r] = acc[i][j];
        }
    }
}

// ---------------- banded attention --------------------------------------
// block: (i-tile of 32, head). band of 230 keys, S in smem, PV jj-split.
#define SK_OFF 0                 // sKt [64][256]
#define SV_OFF 16384             // sV  [240][64]
#define SS_OFF 31744             // sS  [32][256]
#define SQ_OFF 39936             // sQt [64][32] (reused as reduction buf)
#define ATTN_SMEM_FLOATS 41984

__global__ void __launch_bounds__(256) attn_kernel()
{
    extern __shared__ float sm[];
    float* sKt = sm + SK_OFF;
    float* sV  = sm + SV_OFF;
    float* sS  = sm + SS_OFF;
    float* sQt = sm + SQ_OFF;

    int h = blockIdx.y;
    int i0 = blockIdx.x * 32;
    int jlo = i0 - RAD;
    int t = threadIdx.x;

    // zero K/V region (covers invalid / padded rows)
    float4 z4 = make_float4(0.f, 0.f, 0.f, 0.f);
    for (int idx = t; idx < (16384 + 15360) / 4; idx += 256)
        ((float4*)sm)[idx] = z4;
    // load Q transposed (disjoint region, OK concurrently)
    for (int idx = t; idx < 32 * 16; idx += 256) {
        int qi = idx >> 4, dq = (idx & 15) << 2;
        float4 v = *(const float4*)&g_q[((h * Nn + i0 + qi) << 6) + dq];
        sQt[(dq + 0) * 32 + qi] = v.x; sQt[(dq + 1) * 32 + qi] = v.y;
        sQt[(dq + 2) * 32 + qi] = v.z; sQt[(dq + 3) * 32 + qi] = v.w;
    }
    __syncthreads();

    // load K band (transposed) and V band (row-major)
    for (int idx = t; idx < 230 * 16; idx += 256) {
        int jj = idx >> 4, dq = (idx & 15) << 2;
        int j = jlo + jj;
        if (j >= 0 && j < Nn) {
            float4 kv = *(const float4*)&g_k[((h * Nn + j) << 6) + dq];
            sKt[(dq + 0) * 256 + jj] = kv.x; sKt[(dq + 1) * 256 + jj] = kv.y;
            sKt[(dq + 2) * 256 + jj] = kv.z; sKt[(dq + 3) * 256 + jj] = kv.w;
            float4 vv = *(const float4*)&g_v[((h * Nn + j) << 6) + dq];
            *(float4*)&sV[jj * 64 + dq] = vv;
        }
    }
    __syncthreads();

    // ---- S = Q @ Kband^T (k pre-scaled) ----
    {
        int tx = t & 31, ty = t >> 5;
        float acc[4][8];
#pragma unroll
        for (int i = 0; i < 4; i++)
#pragma unroll
            for (int j = 0; j < 8; j++) acc[i][j] = 0.f;
        for (int k = 0; k < 64; k++) {
            float4 a  = *(float4*)&sQt[k * 32 + ty * 4];
            float4 b0 = *(float4*)&sKt[k * 256 + tx * 4];
            float4 b1 = *(float4*)&sKt[k * 256 + 128 + tx * 4];
            float av[4] = {a.x, a.y, a.z, a.w};
            float bv[8] = {b0.x, b0.y, b0.z, b0.w, b1.x, b1.y, b1.z, b1.w};
#pragma unroll
            for (int i = 0; i < 4; i++)
#pragma unroll
                for (int j = 0; j < 8; j++) acc[i][j] += av[i] * bv[j];
        }
#pragma unroll
        for (int i = 0; i < 4; i++) {
            int row = ty * 4 + i;
            *(float4*)&sS[row * 256 + tx * 4]       = make_float4(acc[i][0], acc[i][1], acc[i][2], acc[i][3]);
            *(float4*)&sS[row * 256 + 128 + tx * 4] = make_float4(acc[i][4], acc[i][5], acc[i][6], acc[i][7]);
        }
    }
    __syncthreads();

    // ---- banded softmax, one warp per 4 rows ----
    {
        int lane = t & 31, w = t >> 5;
#pragma unroll
        for (int p = 0; p < 4; p++) {
            int qi = w * 4 + p;
            int i = i0 + qi;
            float v[7];
#pragma unroll
            for (int u = 0; u < 7; u++) {
                int r = lane + u * 32;
                float val = -1e30f;
                if (r < NEMB) {
                    int j = i - RAD + r;
                    if (j >= 0 && j < Nn)
                        val = sS[qi * 256 + qi + r] + g_pos[(size_t)(h * Nn + i) * PST + r];
                }
                v[u] = val;
            }
            __syncwarp();
            float mx = v[0];
#pragma unroll
            for (int u = 1; u < 7; u++) mx = fmaxf(mx, v[u]);
#pragma unroll
            for (int off = 16; off; off >>= 1) mx = fmaxf(mx, __shfl_xor_sync(0xffffffffu, mx, off));
            float e[7], s = 0.f;
#pragma unroll
            for (int u = 0; u < 7; u++) {
                e[u] = (v[u] > -1e29f) ? __expf(v[u] - mx) : 0.f;
                s += e[u];
            }
#pragma unroll
            for (int off = 16; off; off >>= 1) s += __shfl_xor_sync(0xffffffffu, s, off);
            float inv = 1.f / s;
            // zero full row, then write normalized probs at band positions
            for (int c = lane; c < 256; c += 32) sS[qi * 256 + c] = 0.f;
            __syncwarp();
#pragma unroll
            for (int u = 0; u < 7; u++) {
                int r = lane + u * 32;
                if (r < NEMB && e[u] != 0.f) sS[qi * 256 + qi + r] = e[u] * inv;
            }
            __syncwarp();
        }
    }
    __syncthreads();

    // ---- O = P @ Vband, jj split across two thread groups ----
    {
        int g = t >> 7;           // 0 or 1
        int lt = t & 127;
        int ty2 = lt >> 4, tx2 = lt & 15;
        float acc[4][4];
#pragma unroll
        for (int i = 0; i < 4; i++)
#pragma unroll
            for (int j = 0; j < 4; j++) acc[i][j] = 0.f;
        int jb = g * 120, je = jb + 120;
        for (int jj = jb; jj < je; jj++) {
            float4 vv = *(float4*)&sV[jj * 64 + tx2 * 4];
            float vr[4] = {vv.x, vv.y, vv.z, vv.w};
#pragma unroll
            for (int i = 0; i < 4; i++) {
                float pp = sS[(ty2 * 4 + i) * 256 + jj];
#pragma unroll
                for (int j = 0; j < 4; j++) acc[i][j] += pp * vr[j];
            }
        }
        if (g == 1) {
#pragma unroll
            for (int i = 0; i < 4; i++)
#pragma unroll
                for (int j = 0; j < 4; j++) sQt[lt * 16 + i * 4 + j] = acc[i][j];
        }
        __syncthreads();
        if (g == 0) {
#pragma unroll
            for (int i = 0; i < 4; i++) {
                float4 r = *(float4*)&sQt[lt * 16 + i * 4];
                float4 o = make_float4(acc[i][0] + r.x, acc[i][1] + r.y,
                                       acc[i][2] + r.z, acc[i][3] + r.w);
                int n = i0 + ty2 * 4 + i;
                *(float4*)&g_ao[(size_t)n * Dd + h * 64 + tx2 * 4] = o;
            }
        }
    }
}

// ---------------- launcher ------------------------------------------------
extern "C" void kernel_launch(void* const* d_in, const int* in_sizes, int n_in,
                              void* d_out, int out_size)
{
    (void)in_sizes; (void)n_in; (void)out_size;
    const float* x      = (const float*)d_in[0];
    const float* qkv_w  = (const float*)d_in[1];
    const float* qkv_b  = (const float*)d_in[2];
    const float* proj_w = (const float*)d_in[3];
    const float* proj_b = (const float*)d_in[4];
    const float* rel    = (const float*)d_in[5];
    float* out = (float*)d_out;

    cudaFuncSetAttribute(pos_kernel, cudaFuncAttributeMaxDynamicSharedMemorySize,
                         POS_SMEM_FLOATS * 4);
    cudaFuncSetAttribute(attn_kernel, cudaFuncAttributeMaxDynamicSharedMemorySize,
                         ATTN_SMEM_FLOATS * 4);

    // 1) QKV GEMM -> q, k(scaled), v
    sgemm_nt<0><<<dim3(3072 / 128, Nn / 128), 256>>>(x, qkv_w, qkv_b, nullptr,
                                                     Nn, 3 * Dd, Dd);
    // 2) positional logits P[h][i][r]
    pos_kernel<<<dim3(Nn / 32, Hh), 256, POS_SMEM_FLOATS * 4>>>(rel);
    // 3) banded attention -> g_ao
    attn_kernel<<<dim3(Nn / 32, Hh), 256, ATTN_SMEM_FLOATS * 4>>>();
    // 4) output projection -> d_out
    sgemm_nt<1><<<dim3(Dd / 128, Nn / 128), 256>>>(nullptr, proj_w, proj_b, out,
                                                   Nn, Dd, Dd);
}

// round 3
// speedup vs baseline: 1.7294x; 1.7294x over previous
#include <cuda_runtime.h>
#include <cstdint>

#define Nn 2048
#define Dd 1024
#define Hh 16
#define HD 64
#define NEMB 199
#define RAD 99
#define PST 256

// ---------------- scratch (device globals; no allocation) ----------------
__device__ float g_q[Hh * Nn * HD];
__device__ float g_k[Hh * Nn * HD];        // pre-scaled by 1/8
__device__ float g_v[Hh * Nn * HD];
__device__ float g_pos[Hh * Nn * PST];
__device__ float g_ao[Nn * Dd];

// ---------------- tf32 mma.sync GEMM --------------------------------------
// C[row][feat] = sum_k A[row][k] * B[feat][k] (+bias). Both operands K-major.
// MODE 0: feats 3072 -> scatter q/k(scaled)/v. MODE 1: feats 1024 -> out.
#define BM 128
#define BN 128
#define BK 32
#define APITCH 36

__device__ __forceinline__ uint32_t f2tf(float f) {
    uint32_t u;
    asm("cvt.rna.tf32.f32 %0, %1;" : "=r"(u) : "f"(f));
    return u;
}

#define MMA_TF32(d, a, b) \
    asm volatile( \
        "mma.sync.aligned.m16n8k8.row.col.f32.tf32.tf32.f32 " \
        "{%0,%1,%2,%3}, {%4,%5,%6,%7}, {%8,%9}, {%0,%1,%2,%3};" \
        : "+f"((d)[0]), "+f"((d)[1]), "+f"((d)[2]), "+f"((d)[3]) \
        : "r"((a)[0]), "r"((a)[1]), "r"((a)[2]), "r"((a)[3]), \
          "r"((b)[0]), "r"((b)[1]))

template <int MODE>
__global__ void __launch_bounds__(256) mma_gemm(
    const float* __restrict__ Ain, const float* __restrict__ B,
    const float* __restrict__ bias, float* __restrict__ out, int K)
{
    const float* A = (MODE == 1) ? (const float*)g_ao : Ain;
    __shared__ uint32_t As[BM * APITCH];
    __shared__ uint32_t Bs[BN * APITCH];

    const int t = threadIdx.x;
    const int m0 = blockIdx.y * BM;
    const int n0 = blockIdx.x * BN;
    const int w = t >> 5, lane = t & 31;
    const int wy = w >> 2, wx = w & 3;        // 2 x 4 warp grid
    const int gid = lane >> 2, tig = lane & 3;

    float acc[4][4][4];
#pragma unroll
    for (int mi = 0; mi < 4; mi++)
#pragma unroll
        for (int ni = 0; ni < 4; ni++)
#pragma unroll
            for (int j = 0; j < 4; j++) acc[mi][ni][j] = 0.f;

    for (int k0 = 0; k0 < K; k0 += BK) {
#pragma unroll
        for (int q = 0; q < 4; q++) {
            int s = t + q * 256;
            int row = s >> 3, kc = (s & 7) << 2;
            float4 a = *(const float4*)(A + (size_t)(m0 + row) * K + k0 + kc);
            float4 b = *(const float4*)(B + (size_t)(n0 + row) * K + k0 + kc);
            As[row * APITCH + kc + 0] = f2tf(a.x);
            As[row * APITCH + kc + 1] = f2tf(a.y);
            As[row * APITCH + kc + 2] = f2tf(a.z);
            As[row * APITCH + kc + 3] = f2tf(a.w);
            Bs[row * APITCH + kc + 0] = f2tf(b.x);
            Bs[row * APITCH + kc + 1] = f2tf(b.y);
            Bs[row * APITCH + kc + 2] = f2tf(b.z);
            Bs[row * APITCH + kc + 3] = f2tf(b.w);
        }
        __syncthreads();

#pragma unroll
        for (int ks = 0; ks < 4; ks++) {
            int kb = ks * 8 + tig;
            uint32_t af[4][4], bf[4][2];
#pragma unroll
            for (int mi = 0; mi < 4; mi++) {
                int r = wy * 64 + mi * 16 + gid;
                af[mi][0] = As[r * APITCH + kb];
                af[mi][1] = As[(r + 8) * APITCH + kb];
                af[mi][2] = As[r * APITCH + kb + 4];
                af[mi][3] = As[(r + 8) * APITCH + kb + 4];
            }
#pragma unroll
            for (int ni = 0; ni < 4; ni++) {
                int n = wx * 32 + ni * 8 + gid;
                bf[ni][0] = Bs[n * APITCH + kb];
                bf[ni][1] = Bs[n * APITCH + kb + 4];
            }
#pragma unroll
            for (int mi = 0; mi < 4; mi++)
#pragma unroll
                for (int ni = 0; ni < 4; ni++)
                    MMA_TF32(acc[mi][ni], af[mi], bf[ni]);
        }
        __syncthreads();
    }

    // epilogue: each (mi, ni) frag holds rows {r, r+8}, cols {c, c+1}
#pragma unroll
    for (int mi = 0; mi < 4; mi++) {
        int r0 = m0 + wy * 64 + mi * 16 + gid;
#pragma unroll
        for (int ni = 0; ni < 4; ni++) {
            int feat = n0 + wx * 32 + ni * 8 + 2 * tig;
            float2 bb = *(const float2*)&bias[feat];
            if (MODE == 0) {
                int sec = feat >> 10, hm = feat & 1023;
                float* p = (sec == 0) ? g_q : ((sec == 1) ? g_k : g_v);
                float sc = (sec == 1) ? 0.125f : 1.0f;
                int h = hm >> 6, d = hm & 63;
                float2 v0 = make_float2((acc[mi][ni][0] + bb.x) * sc,
                                        (acc[mi][ni][1] + bb.y) * sc);
                float2 v1 = make_float2((acc[mi][ni][2] + bb.x) * sc,
                                        (acc[mi][ni][3] + bb.y) * sc);
                *(float2*)&p[((h * Nn + r0) << 6) + d] = v0;
                *(float2*)&p[((h * Nn + r0 + 8) << 6) + d] = v1;
            } else {
                float2 v0 = make_float2(acc[mi][ni][0] + bb.x, acc[mi][ni][1] + bb.y);
                float2 v1 = make_float2(acc[mi][ni][2] + bb.x, acc[mi][ni][3] + bb.y);
                *(float2*)&out[(size_t)r0 * Dd + feat] = v0;
                *(float2*)&out[(size_t)(r0 + 8) * Dd + feat] = v1;
            }
        }
    }
}

// ---------------- pos logits ----------------------------------------------
#define ESTR 232
#define POS_SMEM_FLOATS (64 * 32 + 64 * ESTR)

__global__ void __launch_bounds__(256) pos_kernel(const float* __restrict__ rel_emb)
{
    extern __shared__ float sm[];
    float* sQt = sm;
    float* sEt = sm + 64 * 32;

    int h = blockIdx.y;
    int i0 = blockIdx.x * 32;
    int t = threadIdx.x;

    for (int idx = t; idx < 32 * 16; idx += 256) {
        int qi = idx >> 4, dq = (idx & 15) << 2;
        float4 v = *(const float4*)&g_q[((h * Nn + i0 + qi) << 6) + dq];
        sQt[(dq + 0) * 32 + qi] = v.x; sQt[(dq + 1) * 32 + qi] = v.y;
        sQt[(dq + 2) * 32 + qi] = v.z; sQt[(dq + 3) * 32 + qi] = v.w;
    }
    const float* E = rel_emb + (size_t)h * NEMB * HD;
    for (int idx = t; idx < NEMB * 16; idx += 256) {
        int r = idx >> 4, dq = (idx & 15) << 2;
        float4 v = *(const float4*)&E[r * HD + dq];
        sEt[(dq + 0) * ESTR + r] = v.x; sEt[(dq + 1) * ESTR + r] = v.y;
        sEt[(dq + 2) * ESTR + r] = v.z; sEt[(dq + 3) * ESTR + r] = v.w;
    }
    __syncthreads();

    int tx = t & 31, ty = t >> 5;
    float acc[4][8];
#pragma unroll
    for (int i = 0; i < 4; i++)
#pragma unroll
        for (int j = 0; j < 8; j++) acc[i][j] = 0.f;

    for (int k = 0; k < 64; k++) {
        float4 a  = *(float4*)&sQt[k * 32 + ty * 4];
        float4 b0 = *(float4*)&sEt[k * ESTR + tx * 4];
        float4 b1 = *(float4*)&sEt[k * ESTR + 104 + tx * 4];
        float av[4] = {a.x, a.y, a.z, a.w};
        float bv[8] = {b0.x, b0.y, b0.z, b0.w, b1.x, b1.y, b1.z, b1.w};
#pragma unroll
        for (int i = 0; i < 4; i++)
#pragma unroll
            for (int j = 0; j < 8; j++) acc[i][j] += av[i] * bv[j];
    }

#pragma unroll
    for (int i = 0; i < 4; i++) {
        int ii = i0 + ty * 4 + i;
#pragma unroll
        for (int j = 0; j < 8; j++) {
            int r = (j < 4) ? (tx * 4 + j) : (104 + tx * 4 + j - 4);
            if (r < NEMB) g_pos[(size_t)(h * Nn + ii) * PST + r] = acc[i][j];
        }
    }
}

// ---------------- banded attention ----------------------------------------
#define SK_OFF 0
#define SV_OFF 16384
#define SS_OFF 31744
#define SQ_OFF 39936
#define ATTN_SMEM_FLOATS 41984

__global__ void __launch_bounds__(256) attn_kernel()
{
    extern __shared__ float sm[];
    float* sKt = sm + SK_OFF;
    float* sV  = sm + SV_OFF;
    float* sS  = sm + SS_OFF;
    float* sQt = sm + SQ_OFF;

    int h = blockIdx.y;
    int i0 = blockIdx.x * 32;
    int jlo = i0 - RAD;
    int t = threadIdx.x;

    float4 z4 = make_float4(0.f, 0.f, 0.f, 0.f);
    for (int idx = t; idx < (16384 + 15360) / 4; idx += 256)
        ((float4*)sm)[idx] = z4;
    for (int idx = t; idx < 32 * 16; idx += 256) {
        int qi = idx >> 4, dq = (idx & 15) << 2;
        float4 v = *(const float4*)&g_q[((h * Nn + i0 + qi) << 6) + dq];
        sQt[(dq + 0) * 32 + qi] = v.x; sQt[(dq + 1) * 32 + qi] = v.y;
        sQt[(dq + 2) * 32 + qi] = v.z; sQt[(dq + 3) * 32 + qi] = v.w;
    }
    __syncthreads();

    for (int idx = t; idx < 230 * 16; idx += 256) {
        int jj = idx >> 4, dq = (idx & 15) << 2;
        int j = jlo + jj;
        if (j >= 0 && j < Nn) {
            float4 kv = *(const float4*)&g_k[((h * Nn + j) << 6) + dq];
            sKt[(dq + 0) * 256 + jj] = kv.x; sKt[(dq + 1) * 256 + jj] = kv.y;
            sKt[(dq + 2) * 256 + jj] = kv.z; sKt[(dq + 3) * 256 + jj] = kv.w;
            float4 vv = *(const float4*)&g_v[((h * Nn + j) << 6) + dq];
            *(float4*)&sV[jj * 64 + dq] = vv;
        }
    }
    __syncthreads();

    {
        int tx = t & 31, ty = t >> 5;
        float acc[4][8];
#pragma unroll
        for (int i = 0; i < 4; i++)
#pragma unroll
            for (int j = 0; j < 8; j++) acc[i][j] = 0.f;
        for (int k = 0; k < 64; k++) {
            float4 a  = *(float4*)&sQt[k * 32 + ty * 4];
            float4 b0 = *(float4*)&sKt[k * 256 + tx * 4];
            float4 b1 = *(float4*)&sKt[k * 256 + 128 + tx * 4];
            float av[4] = {a.x, a.y, a.z, a.w};
            float bv[8] = {b0.x, b0.y, b0.z, b0.w, b1.x, b1.y, b1.z, b1.w};
#pragma unroll
            for (int i = 0; i < 4; i++)
#pragma unroll
                for (int j = 0; j < 8; j++) acc[i][j] += av[i] * bv[j];
        }
#pragma unroll
        for (int i = 0; i < 4; i++) {
            int row = ty * 4 + i;
            *(float4*)&sS[row * 256 + tx * 4]       = make_float4(acc[i][0], acc[i][1], acc[i][2], acc[i][3]);
            *(float4*)&sS[row * 256 + 128 + tx * 4] = make_float4(acc[i][4], acc[i][5], acc[i][6], acc[i][7]);
        }
    }
    __syncthreads();

    {
        int lane = t & 31, w = t >> 5;
#pragma unroll
        for (int p = 0; p < 4; p++) {
            int qi = w * 4 + p;
            int i = i0 + qi;
            float v[7];
#pragma unroll
            for (int u = 0; u < 7; u++) {
                int r = lane + u * 32;
                float val = -1e30f;
                if (r < NEMB) {
                    int j = i - RAD + r;
                    if (j >= 0 && j < Nn)
                        val = sS[qi * 256 + qi + r] + g_pos[(size_t)(h * Nn + i) * PST + r];
                }
                v[u] = val;
            }
            __syncwarp();
            float mx = v[0];
#pragma unroll
            for (int u = 1; u < 7; u++) mx = fmaxf(mx, v[u]);
#pragma unroll
            for (int off = 16; off; off >>= 1) mx = fmaxf(mx, __shfl_xor_sync(0xffffffffu, mx, off));
            float e[7], s = 0.f;
#pragma unroll
            for (int u = 0; u < 7; u++) {
                e[u] = (v[u] > -1e29f) ? __expf(v[u] - mx) : 0.f;
                s += e[u];
            }
#pragma unroll
            for (int off = 16; off; off >>= 1) s += __shfl_xor_sync(0xffffffffu, s, off);
            float inv = 1.f / s;
            for (int c = lane; c < 256; c += 32) sS[qi * 256 + c] = 0.f;
            __syncwarp();
#pragma unroll
            for (int u = 0; u < 7; u++) {
                int r = lane + u * 32;
                if (r < NEMB && e[u] != 0.f) sS[qi * 256 + qi + r] = e[u] * inv;
            }
            __syncwarp();
        }
    }
    __syncthreads();

    {
        int g = t >> 7;
        int lt = t & 127;
        int ty2 = lt >> 4, tx2 = lt & 15;
        float acc[4][4];
#pragma unroll
        for (int i = 0; i < 4; i++)
#pragma unroll
            for (int j = 0; j < 4; j++) acc[i][j] = 0.f;
        int jb = g * 120, je = jb + 120;
        for (int jj = jb; jj < je; jj++) {
            float4 vv = *(float4*)&sV[jj * 64 + tx2 * 4];
            float vr[4] = {vv.x, vv.y, vv.z, vv.w};
#pragma unroll
            for (int i = 0; i < 4; i++) {
                float pp = sS[(ty2 * 4 + i) * 256 + jj];
#pragma unroll
                for (int j = 0; j < 4; j++) acc[i][j] += pp * vr[j];
            }
        }
        if (g == 1) {
#pragma unroll
            for (int i = 0; i < 4; i++)
#pragma unroll
                for (int j = 0; j < 4; j++) sQt[lt * 16 + i * 4 + j] = acc[i][j];
        }
        __syncthreads();
        if (g == 0) {
#pragma unroll
            for (int i = 0; i < 4; i++) {
                float4 r = *(float4*)&sQt[lt * 16 + i * 4];
                float4 o = make_float4(acc[i][0] + r.x, acc[i][1] + r.y,
                                       acc[i][2] + r.z, acc[i][3] + r.w);
                int n = i0 + ty2 * 4 + i;
                *(float4*)&g_ao[(size_t)n * Dd + h * 64 + tx2 * 4] = o;
            }
        }
    }
}

// ---------------- launcher ------------------------------------------------
extern "C" void kernel_launch(void* const* d_in, const int* in_sizes, int n_in,
                              void* d_out, int out_size)
{
    (void)in_sizes; (void)n_in; (void)out_size;
    const float* x      = (const float*)d_in[0];
    const float* qkv_w  = (const float*)d_in[1];
    const float* qkv_b  = (const float*)d_in[2];
    const float* proj_w = (const float*)d_in[3];
    const float* proj_b = (const float*)d_in[4];
    const float* rel    = (const float*)d_in[5];
    float* out = (float*)d_out;

    cudaFuncSetAttribute(pos_kernel, cudaFuncAttributeMaxDynamicSharedMemorySize,
                         POS_SMEM_FLOATS * 4);
    cudaFuncSetAttribute(attn_kernel, cudaFuncAttributeMaxDynamicSharedMemorySize,
                         ATTN_SMEM_FLOATS * 4);

    // 1) QKV GEMM (tf32 mma.sync): scatter q / k(scaled) / v
    mma_gemm<0><<<dim3(3072 / BN, Nn / BM), 256>>>(x, qkv_w, qkv_b, nullptr, Dd);
    // 2) positional logits
    pos_kernel<<<dim3(Nn / 32, Hh), 256, POS_SMEM_FLOATS * 4>>>(rel);
    // 3) banded attention -> g_ao
    attn_kernel<<<dim3(Nn / 32, Hh), 256, ATTN_SMEM_FLOATS * 4>>>();
    // 4) output projection (tf32 mma.sync) -> d_out
    mma_gemm<1><<<dim3(Dd / BN, Nn / BM), 256>>>(nullptr, proj_w, proj_b, out, Dd);
}

// round 4
// speedup vs baseline: 1.9708x; 1.1396x over previous
#include <cuda_runtime.h>
#include <cstdint>

#define Nn 2048
#define Dd 1024
#define Hh 16
#define HD 64
#define NEMB 199
#define RAD 99
#define PST 256

// ---------------- scratch (device globals; no allocation) ----------------
__device__ float g_q[Hh * Nn * HD];
__device__ float g_k[Hh * Nn * HD];        // pre-scaled by 1/8
__device__ float g_v[Hh * Nn * HD];
__device__ float g_pos[Hh * Nn * PST];
__device__ float g_ao[Nn * Dd];

// ---------------- tf32 mma.sync GEMM, cp.async double-buffered ------------
// C[row][feat] = sum_k A[row][k] * B[feat][k] (+bias). Both operands K-major.
// MODE 0: feats 3072 -> scatter q/k(scaled)/v. MODE 1: feats 1024 -> out.
#define BM 128
#define BN 128
#define BK 32
#define GP 36                      // smem row pitch in floats (conflict-free, 16B-mult)
#define STAGE_F (BM * GP)          // 4608 floats per operand stage
#define GEMM_SMEM_BYTES (4 * STAGE_F * 4)   // 73728 B

__device__ __forceinline__ uint32_t f2tf(float f) {
    uint32_t u;
    asm("cvt.rna.tf32.f32 %0, %1;" : "=r"(u) : "f"(f));
    return u;
}
__device__ __forceinline__ uint32_t smem_u32(const void* p) {
    uint32_t a;
    asm("{ .reg .u64 t; cvta.to.shared.u64 t, %1; cvt.u32.u64 %0, t; }"
        : "=r"(a) : "l"(p));
    return a;
}
__device__ __forceinline__ void cp16(uint32_t dst, const void* src) {
    asm volatile("cp.async.cg.shared.global [%0], [%1], 16;" :: "r"(dst), "l"(src) : "memory");
}

#define MMA_TF32(d, a, b) \
    asm volatile( \
        "mma.sync.aligned.m16n8k8.row.col.f32.tf32.tf32.f32 " \
        "{%0,%1,%2,%3}, {%4,%5,%6,%7}, {%8,%9}, {%0,%1,%2,%3};" \
        : "+f"((d)[0]), "+f"((d)[1]), "+f"((d)[2]), "+f"((d)[3]) \
        : "r"((a)[0]), "r"((a)[1]), "r"((a)[2]), "r"((a)[3]), \
          "r"((b)[0]), "r"((b)[1]))

template <int MODE>
__global__ void __launch_bounds__(256) mma_gemm(
    const float* __restrict__ Ain, const float* __restrict__ B,
    const float* __restrict__ bias, float* __restrict__ out, int K)
{
    const float* A = (MODE == 1) ? (const float*)g_ao : Ain;
    extern __shared__ __align__(16) float smem[];
    float* sA = smem;                    // [2][BM*GP]
    float* sB = smem + 2 * STAGE_F;      // [2][BN*GP]
    const uint32_t sAu = smem_u32(sA);
    const uint32_t sBu = smem_u32(sB);

    const int t = threadIdx.x;
    const int m0 = blockIdx.y * BM;
    const int n0 = blockIdx.x * BN;
    const int w = t >> 5, lane = t & 31;
    const int wy = w >> 2, wx = w & 3;        // 2 x 4 warp grid
    const int gid = lane >> 2, tig = lane & 3;

    // per-thread copy coordinates (8 x 16B per operand per chunk)
    const int crow = t >> 3;           // 0..31 (x8 rows via q), actually row = (t + q*256)>>3
    (void)crow;

    float acc[4][4][4];
#pragma unroll
    for (int mi = 0; mi < 4; mi++)
#pragma unroll
        for (int ni = 0; ni < 4; ni++)
#pragma unroll
            for (int j = 0; j < 4; j++) acc[mi][ni][j] = 0.f;

    const int nc = K / BK;

    auto load_chunk = [&](int c, int s) {
        const float* Ap = A + (size_t)m0 * K + c * BK;
        const float* Bp = B + (size_t)n0 * K + c * BK;
        uint32_t ab = sAu + (uint32_t)s * (STAGE_F * 4);
        uint32_t bb = sBu + (uint32_t)s * (STAGE_F * 4);
#pragma unroll
        for (int q = 0; q < 4; q++) {
            int idx = t + q * 256;            // 0..1023
            int row = idx >> 3, c16 = idx & 7;
            uint32_t soff = (uint32_t)(row * GP + c16 * 4) * 4;
            size_t goff = (size_t)row * K + c16 * 4;
            cp16(ab + soff, Ap + goff);
            cp16(bb + soff, Bp + goff);
        }
    };

    load_chunk(0, 0);
    asm volatile("cp.async.commit_group;" ::: "memory");

    for (int c = 0; c < nc; ++c) {
        int s = c & 1;
        if (c + 1 < nc) {
            load_chunk(c + 1, s ^ 1);
            asm volatile("cp.async.commit_group;" ::: "memory");
            asm volatile("cp.async.wait_group 1;" ::: "memory");
        } else {
            asm volatile("cp.async.wait_group 0;" ::: "memory");
        }
        __syncthreads();

        const float* As = sA + s * STAGE_F;
        const float* Bs = sB + s * STAGE_F;
#pragma unroll
        for (int ks = 0; ks < 4; ks++) {
            int kb = ks * 8 + tig;
            uint32_t af[4][4], bf[4][2];
#pragma unroll
            for (int mi = 0; mi < 4; mi++) {
                int r = wy * 64 + mi * 16 + gid;
                af[mi][0] = f2tf(As[r * GP + kb]);
                af[mi][1] = f2tf(As[(r + 8) * GP + kb]);
                af[mi][2] = f2tf(As[r * GP + kb + 4]);
                af[mi][3] = f2tf(As[(r + 8) * GP + kb + 4]);
            }
#pragma unroll
            for (int ni = 0; ni < 4; ni++) {
                int n = wx * 32 + ni * 8 + gid;
                bf[ni][0] = f2tf(Bs[n * GP + kb]);
                bf[ni][1] = f2tf(Bs[n * GP + kb + 4]);
            }
#pragma unroll
            for (int mi = 0; mi < 4; mi++)
#pragma unroll
                for (int ni = 0; ni < 4; ni++)
                    MMA_TF32(acc[mi][ni], af[mi], bf[ni]);
        }
        __syncthreads();   // stage s free for the load issued next iteration
    }

    // epilogue: each (mi, ni) frag holds rows {r, r+8}, cols {c, c+1}
#pragma unroll
    for (int mi = 0; mi < 4; mi++) {
        int r0 = m0 + wy * 64 + mi * 16 + gid;
#pragma unroll
        for (int ni = 0; ni < 4; ni++) {
            int feat = n0 + wx * 32 + ni * 8 + 2 * tig;
            float2 bb = *(const float2*)&bias[feat];
            if (MODE == 0) {
                int sec = feat >> 10, hm = feat & 1023;
                float* p = (sec == 0) ? g_q : ((sec == 1) ? g_k : g_v);
                float sc = (sec == 1) ? 0.125f : 1.0f;
                int h = hm >> 6, d = hm & 63;
                float2 v0 = make_float2((acc[mi][ni][0] + bb.x) * sc,
                                        (acc[mi][ni][1] + bb.y) * sc);
                float2 v1 = make_float2((acc[mi][ni][2] + bb.x) * sc,
                                        (acc[mi][ni][3] + bb.y) * sc);
                *(float2*)&p[((h * Nn + r0) << 6) + d] = v0;
                *(float2*)&p[((h * Nn + r0 + 8) << 6) + d] = v1;
            } else {
                float2 v0 = make_float2(acc[mi][ni][0] + bb.x, acc[mi][ni][1] + bb.y);
                float2 v1 = make_float2(acc[mi][ni][2] + bb.x, acc[mi][ni][3] + bb.y);
                *(float2*)&out[(size_t)r0 * Dd + feat] = v0;
                *(float2*)&out[(size_t)(r0 + 8) * Dd + feat] = v1;
            }
        }
    }
}

// ---------------- pos logits ----------------------------------------------
#define ESTR 232
#define POS_SMEM_FLOATS (64 * 32 + 64 * ESTR)

__global__ void __launch_bounds__(256) pos_kernel(const float* __restrict__ rel_emb)
{
    extern __shared__ float sm[];
    float* sQt = sm;
    float* sEt = sm + 64 * 32;

    int h = blockIdx.y;
    int i0 = blockIdx.x * 32;
    int t = threadIdx.x;

    for (int idx = t; idx < 32 * 16; idx += 256) {
        int qi = idx >> 4, dq = (idx & 15) << 2;
        float4 v = *(const float4*)&g_q[((h * Nn + i0 + qi) << 6) + dq];
        sQt[(dq + 0) * 32 + qi] = v.x; sQt[(dq + 1) * 32 + qi] = v.y;
        sQt[(dq + 2) * 32 + qi] = v.z; sQt[(dq + 3) * 32 + qi] = v.w;
    }
    const float* E = rel_emb + (size_t)h * NEMB * HD;
    for (int idx = t; idx < NEMB * 16; idx += 256) {
        int r = idx >> 4, dq = (idx & 15) << 2;
        float4 v = *(const float4*)&E[r * HD + dq];
        sEt[(dq + 0) * ESTR + r] = v.x; sEt[(dq + 1) * ESTR + r] = v.y;
        sEt[(dq + 2) * ESTR + r] = v.z; sEt[(dq + 3) * ESTR + r] = v.w;
    }
    __syncthreads();

    int tx = t & 31, ty = t >> 5;
    float acc[4][8];
#pragma unroll
    for (int i = 0; i < 4; i++)
#pragma unroll
        for (int j = 0; j < 8; j++) acc[i][j] = 0.f;

    for (int k = 0; k < 64; k++) {
        float4 a  = *(float4*)&sQt[k * 32 + ty * 4];
        float4 b0 = *(float4*)&sEt[k * ESTR + tx * 4];
        float4 b1 = *(float4*)&sEt[k * ESTR + 104 + tx * 4];
        float av[4] = {a.x, a.y, a.z, a.w};
        float bv[8] = {b0.x, b0.y, b0.z, b0.w, b1.x, b1.y, b1.z, b1.w};
#pragma unroll
        for (int i = 0; i < 4; i++)
#pragma unroll
            for (int j = 0; j < 8; j++) acc[i][j] += av[i] * bv[j];
    }

#pragma unroll
    for (int i = 0; i < 4; i++) {
        int ii = i0 + ty * 4 + i;
#pragma unroll
        for (int j = 0; j < 8; j++) {
            int r = (j < 4) ? (tx * 4 + j) : (104 + tx * 4 + j - 4);
            if (r < NEMB) g_pos[(size_t)(h * Nn + ii) * PST + r] = acc[i][j];
        }
    }
}

// ---------------- banded attention ----------------------------------------
#define SK_OFF 0
#define SV_OFF 16384
#define SS_OFF 31744
#define SQ_OFF 39936
#define ATTN_SMEM_FLOATS 41984

__global__ void __launch_bounds__(256) attn_kernel()
{
    extern __shared__ float sm[];
    float* sKt = sm + SK_OFF;
    float* sV  = sm + SV_OFF;
    float* sS  = sm + SS_OFF;
    float* sQt = sm + SQ_OFF;

    int h = blockIdx.y;
    int i0 = blockIdx.x * 32;
    int jlo = i0 - RAD;
    int t = threadIdx.x;

    float4 z4 = make_float4(0.f, 0.f, 0.f, 0.f);
    for (int idx = t; idx < (16384 + 15360) / 4; idx += 256)
        ((float4*)sm)[idx] = z4;
    for (int idx = t; idx < 32 * 16; idx += 256) {
        int qi = idx >> 4, dq = (idx & 15) << 2;
        float4 v = *(const float4*)&g_q[((h * Nn + i0 + qi) << 6) + dq];
        sQt[(dq + 0) * 32 + qi] = v.x; sQt[(dq + 1) * 32 + qi] = v.y;
        sQt[(dq + 2) * 32 + qi] = v.z; sQt[(dq + 3) * 32 + qi] = v.w;
    }
    __syncthreads();

    for (int idx = t; idx < 230 * 16; idx += 256) {
        int jj = idx >> 4, dq = (idx & 15) << 2;
        int j = jlo + jj;
        if (j >= 0 && j < Nn) {
            float4 kv = *(const float4*)&g_k[((h * Nn + j) << 6) + dq];
            sKt[(dq + 0) * 256 + jj] = kv.x; sKt[(dq + 1) * 256 + jj] = kv.y;
            sKt[(dq + 2) * 256 + jj] = kv.z; sKt[(dq + 3) * 256 + jj] = kv.w;
            float4 vv = *(const float4*)&g_v[((h * Nn + j) << 6) + dq];
            *(float4*)&sV[jj * 64 + dq] = vv;
        }
    }
    __syncthreads();

    {
        int tx = t & 31, ty = t >> 5;
        float acc[4][8];
#pragma unroll
        for (int i = 0; i < 4; i++)
#pragma unroll
            for (int j = 0; j < 8; j++) acc[i][j] = 0.f;
        for (int k = 0; k < 64; k++) {
            float4 a  = *(float4*)&sQt[k * 32 + ty * 4];
            float4 b0 = *(float4*)&sKt[k * 256 + tx * 4];
            float4 b1 = *(float4*)&sKt[k * 256 + 128 + tx * 4];
            float av[4] = {a.x, a.y, a.z, a.w};
            float bv[8] = {b0.x, b0.y, b0.z, b0.w, b1.x, b1.y, b1.z, b1.w};
#pragma unroll
            for (int i = 0; i < 4; i++)
#pragma unroll
                for (int j = 0; j < 8; j++) acc[i][j] += av[i] * bv[j];
        }
#pragma unroll
        for (int i = 0; i < 4; i++) {
            int row = ty * 4 + i;
            *(float4*)&sS[row * 256 + tx * 4]       = make_float4(acc[i][0], acc[i][1], acc[i][2], acc[i][3]);
            *(float4*)&sS[row * 256 + 128 + tx * 4] = make_float4(acc[i][4], acc[i][5], acc[i][6], acc[i][7]);
        }
    }
    __syncthreads();

    {
        int lane = t & 31, w = t >> 5;
#pragma unroll
        for (int p = 0; p < 4; p++) {
            int qi = w * 4 + p;
            int i = i0 + qi;
            float v[7];
#pragma unroll
            for (int u = 0; u < 7; u++) {
                int r = lane + u * 32;
                float val = -1e30f;
                if (r < NEMB) {
                    int j = i - RAD + r;
                    if (j >= 0 && j < Nn)
                        val = sS[qi * 256 + qi + r] + g_pos[(size_t)(h * Nn + i) * PST + r];
                }
                v[u] = val;
            }
            __syncwarp();
            float mx = v[0];
#pragma unroll
            for (int u = 1; u < 7; u++) mx = fmaxf(mx, v[u]);
#pragma unroll
            for (int off = 16; off; off >>= 1) mx = fmaxf(mx, __shfl_xor_sync(0xffffffffu, mx, off));
            float e[7], s = 0.f;
#pragma unroll
            for (int u = 0; u < 7; u++) {
                e[u] = (v[u] > -1e29f) ? __expf(v[u] - mx) : 0.f;
                s += e[u];
            }
#pragma unroll
            for (int off = 16; off; off >>= 1) s += __shfl_xor_sync(0xffffffffu, s, off);
            float inv = 1.f / s;
            for (int c = lane; c < 256; c += 32) sS[qi * 256 + c] = 0.f;
            __syncwarp();
#pragma unroll
            for (int u = 0; u < 7; u++) {
                int r = lane + u * 32;
                if (r < NEMB && e[u] != 0.f) sS[qi * 256 + qi + r] = e[u] * inv;
            }
            __syncwarp();
        }
    }
    __syncthreads();

    {
        int g = t >> 7;
        int lt = t & 127;
        int ty2 = lt >> 4, tx2 = lt & 15;
        float acc[4][4];
#pragma unroll
        for (int i = 0; i < 4; i++)
#pragma unroll
            for (int j = 0; j < 4; j++) acc[i][j] = 0.f;
        int jb = g * 120, je = jb + 120;
        for (int jj = jb; jj < je; jj++) {
            float4 vv = *(float4*)&sV[jj * 64 + tx2 * 4];
            float vr[4] = {vv.x, vv.y, vv.z, vv.w};
#pragma unroll
            for (int i = 0; i < 4; i++) {
                float pp = sS[(ty2 * 4 + i) * 256 + jj];
#pragma unroll
                for (int j = 0; j < 4; j++) acc[i][j] += pp * vr[j];
            }
        }
        if (g == 1) {
#pragma unroll
            for (int i = 0; i < 4; i++)
#pragma unroll
                for (int j = 0; j < 4; j++) sQt[lt * 16 + i * 4 + j] = acc[i][j];
        }
        __syncthreads();
        if (g == 0) {
#pragma unroll
            for (int i = 0; i < 4; i++) {
                float4 r = *(float4*)&sQt[lt * 16 + i * 4];
                float4 o = make_float4(acc[i][0] + r.x, acc[i][1] + r.y,
                                       acc[i][2] + r.z, acc[i][3] + r.w);
                int n = i0 + ty2 * 4 + i;
                *(float4*)&g_ao[(size_t)n * Dd + h * 64 + tx2 * 4] = o;
            }
        }
    }
}

// ---------------- launcher ------------------------------------------------
extern "C" void kernel_launch(void* const* d_in, const int* in_sizes, int n_in,
                              void* d_out, int out_size)
{
    (void)in_sizes; (void)n_in; (void)out_size;
    const float* x      = (const float*)d_in[0];
    const float* qkv_w  = (const float*)d_in[1];
    const float* qkv_b  = (const float*)d_in[2];
    const float* proj_w = (const float*)d_in[3];
    const float* proj_b = (const float*)d_in[4];
    const float* rel    = (const float*)d_in[5];
    float* out = (float*)d_out;

    cudaFuncSetAttribute(mma_gemm<0>, cudaFuncAttributeMaxDynamicSharedMemorySize,
                         GEMM_SMEM_BYTES);
    cudaFuncSetAttribute(mma_gemm<1>, cudaFuncAttributeMaxDynamicSharedMemorySize,
                         GEMM_SMEM_BYTES);
    cudaFuncSetAttribute(pos_kernel, cudaFuncAttributeMaxDynamicSharedMemorySize,
                         POS_SMEM_FLOATS * 4);
    cudaFuncSetAttribute(attn_kernel, cudaFuncAttributeMaxDynamicSharedMemorySize,
                         ATTN_SMEM_FLOATS * 4);

    // 1) QKV GEMM (tf32 mma.sync, cp.async pipelined): scatter q / k(scaled) / v
    mma_gemm<0><<<dim3(3072 / BN, Nn / BM), 256, GEMM_SMEM_BYTES>>>(x, qkv_w, qkv_b,
                                                                    nullptr, Dd);
    // 2) positional logits
    pos_kernel<<<dim3(Nn / 32, Hh), 256, POS_SMEM_FLOATS * 4>>>(rel);
    // 3) banded attention -> g_ao
    attn_kernel<<<dim3(Nn / 32, Hh), 256, ATTN_SMEM_FLOATS * 4>>>();
    // 4) output projection (tf32 mma.sync) -> d_out
    mma_gemm<1><<<dim3(Dd / BN, Nn / BM), 256, GEMM_SMEM_BYTES>>>(nullptr, proj_w,
                                                                  proj_b, out, Dd);
}

// round 5
// speedup vs baseline: 2.5084x; 1.2728x over previous
#include <cuda_runtime.h>
#include <cstdint>

#define Nn 2048
#define Dd 1024
#define Hh 16
#define HD 64
#define NEMB 199
#define RAD 99

// ---------------- scratch (device globals; no allocation) ----------------
__device__ float g_q[Hh * Nn * HD];
__device__ float g_k[Hh * Nn * HD];        // pre-scaled by 1/8, bias included
__device__ float g_v[Hh * Nn * HD];
__device__ float g_ao[Nn * Dd];

// ---------------- common helpers ------------------------------------------
__device__ __forceinline__ uint32_t f2tf(float f) {
    uint32_t u;
    asm("cvt.rna.tf32.f32 %0, %1;" : "=r"(u) : "f"(f));
    return u;
}
__device__ __forceinline__ uint32_t smem_u32(const void* p) {
    uint32_t a;
    asm("{ .reg .u64 t; cvta.to.shared.u64 t, %1; cvt.u32.u64 %0, t; }"
        : "=r"(a) : "l"(p));
    return a;
}
__device__ __forceinline__ void cp16(uint32_t dst, const void* src) {
    asm volatile("cp.async.cg.shared.global [%0], [%1], 16;" :: "r"(dst), "l"(src) : "memory");
}

#define MMA_TF32(d, a, b) \
    asm volatile( \
        "mma.sync.aligned.m16n8k8.row.col.f32.tf32.tf32.f32 " \
        "{%0,%1,%2,%3}, {%4,%5,%6,%7}, {%8,%9}, {%0,%1,%2,%3};" \
        : "+f"((d)[0]), "+f"((d)[1]), "+f"((d)[2]), "+f"((d)[3]) \
        : "r"((a)[0]), "r"((a)[1]), "r"((a)[2]), "r"((a)[3]), \
          "r"((b)[0]), "r"((b)[1]))

// ---------------- tf32 mma.sync GEMM, cp.async double-buffered ------------
#define BM 128
#define BN 128
#define BK 32
#define GP 36
#define STAGE_F (BM * GP)
#define GEMM_SMEM_BYTES (4 * STAGE_F * 4)

template <int MODE>
__global__ void __launch_bounds__(256) mma_gemm(
    const float* __restrict__ Ain, const float* __restrict__ B,
    const float* __restrict__ bias, float* __restrict__ out, int K)
{
    const float* A = (MODE == 1) ? (const float*)g_ao : Ain;
    extern __shared__ __align__(16) float smem[];
    float* sA = smem;
    float* sB = smem + 2 * STAGE_F;
    const uint32_t sAu = smem_u32(sA);
    const uint32_t sBu = smem_u32(sB);

    const int t = threadIdx.x;
    const int m0 = blockIdx.y * BM;
    const int n0 = blockIdx.x * BN;
    const int w = t >> 5, lane = t & 31;
    const int wy = w >> 2, wx = w & 3;
    const int gid = lane >> 2, tig = lane & 3;

    float acc[4][4][4];
#pragma unroll
    for (int mi = 0; mi < 4; mi++)
#pragma unroll
        for (int ni = 0; ni < 4; ni++)
#pragma unroll
            for (int j = 0; j < 4; j++) acc[mi][ni][j] = 0.f;

    const int nc = K / BK;

    auto load_chunk = [&](int c, int s) {
        const float* Ap = A + (size_t)m0 * K + c * BK;
        const float* Bp = B + (size_t)n0 * K + c * BK;
        uint32_t ab = sAu + (uint32_t)s * (STAGE_F * 4);
        uint32_t bb = sBu + (uint32_t)s * (STAGE_F * 4);
#pragma unroll
        for (int q = 0; q < 4; q++) {
            int idx = t + q * 256;
            int row = idx >> 3, c16 = idx & 7;
            uint32_t soff = (uint32_t)(row * GP + c16 * 4) * 4;
            size_t goff = (size_t)row * K + c16 * 4;
            cp16(ab + soff, Ap + goff);
            cp16(bb + soff, Bp + goff);
        }
    };

    load_chunk(0, 0);
    asm volatile("cp.async.commit_group;" ::: "memory");

    for (int c = 0; c < nc; ++c) {
        int s = c & 1;
        if (c + 1 < nc) {
            load_chunk(c + 1, s ^ 1);
            asm volatile("cp.async.commit_group;" ::: "memory");
            asm volatile("cp.async.wait_group 1;" ::: "memory");
        } else {
            asm volatile("cp.async.wait_group 0;" ::: "memory");
        }
        __syncthreads();

        const float* As = sA + s * STAGE_F;
        const float* Bs = sB + s * STAGE_F;
#pragma unroll
        for (int ks = 0; ks < 4; ks++) {
            int kb = ks * 8 + tig;
            uint32_t af[4][4], bf[4][2];
#pragma unroll
            for (int mi = 0; mi < 4; mi++) {
                int r = wy * 64 + mi * 16 + gid;
                af[mi][0] = f2tf(As[r * GP + kb]);
                af[mi][1] = f2tf(As[(r + 8) * GP + kb]);
                af[mi][2] = f2tf(As[r * GP + kb + 4]);
                af[mi][3] = f2tf(As[(r + 8) * GP + kb + 4]);
            }
#pragma unroll
            for (int ni = 0; ni < 4; ni++) {
                int n = wx * 32 + ni * 8 + gid;
                bf[ni][0] = f2tf(Bs[n * GP + kb]);
                bf[ni][1] = f2tf(Bs[n * GP + kb + 4]);
            }
#pragma unroll
            for (int mi = 0; mi < 4; mi++)
#pragma unroll
                for (int ni = 0; ni < 4; ni++)
                    MMA_TF32(acc[mi][ni], af[mi], bf[ni]);
        }
        __syncthreads();
    }

#pragma unroll
    for (int mi = 0; mi < 4; mi++) {
        int r0 = m0 + wy * 64 + mi * 16 + gid;
#pragma unroll
        for (int ni = 0; ni < 4; ni++) {
            int feat = n0 + wx * 32 + ni * 8 + 2 * tig;
            float2 bb = *(const float2*)&bias[feat];
            if (MODE == 0) {
                int sec = feat >> 10, hm = feat & 1023;
                float* p = (sec == 0) ? g_q : ((sec == 1) ? g_k : g_v);
                float sc = (sec == 1) ? 0.125f : 1.0f;
                int h = hm >> 6, d = hm & 63;
                float2 v0 = make_float2((acc[mi][ni][0] + bb.x) * sc,
                                        (acc[mi][ni][1] + bb.y) * sc);
                float2 v1 = make_float2((acc[mi][ni][2] + bb.x) * sc,
                                        (acc[mi][ni][3] + bb.y) * sc);
                *(float2*)&p[((h * Nn + r0) << 6) + d] = v0;
                *(float2*)&p[((h * Nn + r0 + 8) << 6) + d] = v1;
            } else {
                float2 v0 = make_float2(acc[mi][ni][0] + bb.x, acc[mi][ni][1] + bb.y);
                float2 v1 = make_float2(acc[mi][ni][2] + bb.x, acc[mi][ni][3] + bb.y);
                *(float2*)&out[(size_t)r0 * Dd + feat] = v0;
                *(float2*)&out[(size_t)(r0 + 8) * Dd + feat] = v1;
            }
        }
    }
}

// ---------------- fused banded attention + pos logits (tf32 mma) ----------
// Block = (32-query tile, head). B = [K-band 240 rows ; rel_emb 208 rows],
// S_all(32x448) = Q @ B^T in one MMA sweep; banded softmax; O = P @ V.
#define BP 68          // pitch of sQ / sB rows (floats)
#define SSP 460        // pitch of sS rows (floats)
#define SQ_F (32 * BP)            // 2176
#define SB_F (448 * BP)           // 30464
#define SS_F (32 * SSP)           // 14720
#define ATTN_SMEM_BYTES ((SQ_F + SB_F + SS_F) * 4)   // 189440

__global__ void __launch_bounds__(256) attn_kernel(const float* __restrict__ rel_emb)
{
    extern __shared__ __align__(16) float sm[];
    float* sQ = sm;                    // [32][BP]
    float* sB = sm + SQ_F;             // [448][BP] : rows 0..239 K-band (later V), 240..447 E
    float* sS = sm + SQ_F + SB_F;      // [32][SSP] : cols 0..239 Sqk->P, 240..447 Spos

    const int h = blockIdx.y;
    const int i0 = blockIdx.x * 32;
    const int jlo = i0 - RAD;
    const int t = threadIdx.x;
    const int w = t >> 5, lane = t & 31;
    const int gid = lane >> 2, tig = lane & 3;

    // ---- load Q (32x64) ----
    for (int idx = t; idx < 32 * 16; idx += 256) {
        int qi = idx >> 4, d4 = (idx & 15) << 2;
        *(float4*)&sQ[qi * BP + d4] =
            *(const float4*)&g_q[((h * Nn + i0 + qi) << 6) + d4];
    }
    // ---- load K band rows 0..239 (zero out-of-range) ----
    for (int idx = t; idx < 240 * 16; idx += 256) {
        int jj = idx >> 4, d4 = (idx & 15) << 2;
        int j = jlo + jj;
        float4 v = make_float4(0.f, 0.f, 0.f, 0.f);
        if (j >= 0 && j < Nn)
            v = *(const float4*)&g_k[((h * Nn + j) << 6) + d4];
        *(float4*)&sB[jj * BP + d4] = v;
    }
    // ---- load rel_emb rows 240..447 (199 valid, rest zero) ----
    const float* E = rel_emb + (size_t)h * NEMB * HD;
    for (int idx = t; idx < 208 * 16; idx += 256) {
        int r = idx >> 4, d4 = (idx & 15) << 2;
        float4 v = make_float4(0.f, 0.f, 0.f, 0.f);
        if (r < NEMB) v = *(const float4*)&E[r * HD + d4];
        *(float4*)&sB[(240 + r) * BP + d4] = v;
    }
    __syncthreads();

    // ---- S_all = Q @ B^T : warps cover 56 n8-frags (7 each) ----
    {
        float acc[2][7][4];
#pragma unroll
        for (int mi = 0; mi < 2; mi++)
#pragma unroll
            for (int f = 0; f < 7; f++)
#pragma unroll
                for (int j = 0; j < 4; j++) acc[mi][f][j] = 0.f;

#pragma unroll
        for (int ks = 0; ks < 8; ks++) {
            int kb = ks * 8 + tig;
            uint32_t af[2][4];
#pragma unroll
            for (int mi = 0; mi < 2; mi++) {
                af[mi][0] = f2tf(sQ[(mi * 16 + gid) * BP + kb]);
                af[mi][1] = f2tf(sQ[(mi * 16 + gid + 8) * BP + kb]);
                af[mi][2] = f2tf(sQ[(mi * 16 + gid) * BP + kb + 4]);
                af[mi][3] = f2tf(sQ[(mi * 16 + gid + 8) * BP + kb + 4]);
            }
#pragma unroll
            for (int f = 0; f < 7; f++) {
                int n0 = (w * 7 + f) * 8;
                uint32_t bf[2];
                bf[0] = f2tf(sB[(n0 + gid) * BP + kb]);
                bf[1] = f2tf(sB[(n0 + gid) * BP + kb + 4]);
                MMA_TF32(acc[0][f], af[0], bf);
                MMA_TF32(acc[1][f], af[1], bf);
            }
        }
#pragma unroll
        for (int mi = 0; mi < 2; mi++) {
            int r0 = mi * 16 + gid;
#pragma unroll
            for (int f = 0; f < 7; f++) {
                int col = (w * 7 + f) * 8 + 2 * tig;
                *(float2*)&sS[r0 * SSP + col] = make_float2(acc[mi][f][0], acc[mi][f][1]);
                *(float2*)&sS[(r0 + 8) * SSP + col] = make_float2(acc[mi][f][2], acc[mi][f][3]);
            }
        }
    }
    __syncthreads();

    // ---- overwrite sB rows 0..239 with V band (zero invalid) ----
    for (int idx = t; idx < 240 * 16; idx += 256) {
        int jj = idx >> 4, d4 = (idx & 15) << 2;
        int j = jlo + jj;
        float4 v = make_float4(0.f, 0.f, 0.f, 0.f);
        if (j >= 0 && j < Nn)
            v = *(const float4*)&g_v[((h * Nn + j) << 6) + d4];
        *(float4*)&sB[jj * BP + d4] = v;
    }

    // ---- banded softmax: warp w owns rows w*4..w*4+3 (exclusive) ----
    {
#pragma unroll
        for (int p = 0; p < 4; p++) {
            int qi = w * 4 + p;
            int i = i0 + qi;
            float v[7];
#pragma unroll
            for (int u = 0; u < 7; u++) {
                int r = lane + u * 32;
                float val = -1e30f;
                if (r < NEMB) {
                    int j = i - RAD + r;
                    if (j >= 0 && j < Nn)
                        val = sS[qi * SSP + qi + r] + sS[qi * SSP + 240 + r];
                }
                v[u] = val;
            }
            __syncwarp();
            float mx = v[0];
#pragma unroll
            for (int u = 1; u < 7; u++) mx = fmaxf(mx, v[u]);
#pragma unroll
            for (int off = 16; off; off >>= 1) mx = fmaxf(mx, __shfl_xor_sync(0xffffffffu, mx, off));
            float e[7], s = 0.f;
#pragma unroll
            for (int u = 0; u < 7; u++) {
                e[u] = (v[u] > -1e29f) ? __expf(v[u] - mx) : 0.f;
                s += e[u];
            }
#pragma unroll
            for (int off = 16; off; off >>= 1) s += __shfl_xor_sync(0xffffffffu, s, off);
            float inv = 1.f / s;
            for (int c = lane; c < 240; c += 32) sS[qi * SSP + c] = 0.f;
            __syncwarp();
#pragma unroll
            for (int u = 0; u < 7; u++) {
                int r = lane + u * 32;
                if (r < NEMB && e[u] != 0.f) sS[qi * SSP + qi + r] = e[u] * inv;
            }
            __syncwarp();
        }
    }
    __syncthreads();

    // ---- O = P(32x240) @ V(240x64) : warp w owns d-cols w*8..w*8+7 ----
    {
        float acc[2][4];
#pragma unroll
        for (int mi = 0; mi < 2; mi++)
#pragma unroll
            for (int j = 0; j < 4; j++) acc[mi][j] = 0.f;

        int nd = w * 8 + gid;
#pragma unroll
        for (int ks = 0; ks < 30; ks++) {
            int kb = ks * 8 + tig;
            uint32_t af[2][4];
#pragma unroll
            for (int mi = 0; mi < 2; mi++) {
                af[mi][0] = f2tf(sS[(mi * 16 + gid) * SSP + kb]);
                af[mi][1] = f2tf(sS[(mi * 16 + gid + 8) * SSP + kb]);
                af[mi][2] = f2tf(sS[(mi * 16 + gid) * SSP + kb + 4]);
                af[mi][3] = f2tf(sS[(mi * 16 + gid + 8) * SSP + kb + 4]);
            }
            uint32_t bf[2];
            bf[0] = f2tf(sB[kb * BP + nd]);
            bf[1] = f2tf(sB[(kb + 4) * BP + nd]);
            MMA_TF32(acc[0], af[0], bf);
            MMA_TF32(acc[1], af[1], bf);
        }
#pragma unroll
        for (int mi = 0; mi < 2; mi++) {
            int row = mi * 16 + gid;
            int dcol = h * 64 + w * 8 + 2 * tig;
            *(float2*)&g_ao[(size_t)(i0 + row) * Dd + dcol] =
                make_float2(acc[mi][0], acc[mi][1]);
            *(float2*)&g_ao[(size_t)(i0 + row + 8) * Dd + dcol] =
                make_float2(acc[mi][2], acc[mi][3]);
        }
    }
}

// ---------------- launcher ------------------------------------------------
extern "C" void kernel_launch(void* const* d_in, const int* in_sizes, int n_in,
                              void* d_out, int out_size)
{
    (void)in_sizes; (void)n_in; (void)out_size;
    const float* x      = (const float*)d_in[0];
    const float* qkv_w  = (const float*)d_in[1];
    const float* qkv_b  = (const float*)d_in[2];
    const float* proj_w = (const float*)d_in[3];
    const float* proj_b = (const float*)d_in[4];
    const float* rel    = (const float*)d_in[5];
    float* out = (float*)d_out;

    cudaFuncSetAttribute(mma_gemm<0>, cudaFuncAttributeMaxDynamicSharedMemorySize,
                         GEMM_SMEM_BYTES);
    cudaFuncSetAttribute(mma_gemm<1>, cudaFuncAttributeMaxDynamicSharedMemorySize,
                         GEMM_SMEM_BYTES);
    cudaFuncSetAttribute(attn_kernel, cudaFuncAttributeMaxDynamicSharedMemorySize,
                         ATTN_SMEM_BYTES);

    // 1) QKV GEMM (tf32 mma.sync, cp.async pipelined): scatter q / k(scaled) / v
    mma_gemm<0><<<dim3(3072 / BN, Nn / BM), 256, GEMM_SMEM_BYTES>>>(x, qkv_w, qkv_b,
                                                                    nullptr, Dd);
    // 2) fused pos + banded attention (tf32 mma) -> g_ao
    attn_kernel<<<dim3(Nn / 32, Hh), 256, ATTN_SMEM_BYTES>>>(rel);
    // 3) output projection (tf32 mma.sync) -> d_out
    mma_gemm<1><<<dim3(Dd / BN, Nn / BM), 256, GEMM_SMEM_BYTES>>>(nullptr, proj_w,
                                                                  proj_b, out, Dd);
}